// round 15
// baseline (speedup 1.0000x reference)
#include <cuda_runtime.h>
#include <cuda_bf16.h>

// HungarianMatcher cost matrix, 19200 rows x 1280 targets, fp32.
//
// 1D-GIoU collapse + ratio rewrite:
//   cost = |dc| + 2|hd| + (cc + cr - 1) + m/den
//   dc = cx-tc, hd = hw-htw (hw=0.5w), m = max(|dc|,|hd|), den = 0.5(hs+m)
// 9 instrs/element. This round: ILP, not arithmetic —
//   * 8 targets/thread (160-thread blocks): 72 independent ops per LDS broadcast
//   * QPER=16, grid=1200: up to 12 resident blocks/SM (~94% theoretical occ)
//   * row-constant software pipelining (prefetch q+1 before computing q)

#define QPER 16
#define NTHREADS 160
#define TPT 8              // targets per thread
#define TT 1280
#define NROWS 19200

__device__ __forceinline__ float rcp_fast(float x) {
    float r; asm("rcp.approx.f32 %0, %1;" : "=f"(r) : "f"(x)); return r;
}

__device__ __forceinline__ float cost_el(float cx, float hw, float hqq, float C,
                                         float tc, float htw)
{
    float dc   = cx - tc;                      // FADD
    float hd   = hw - htw;                     // FADD
    float hs_h = fmaf(htw, 0.5f, hqq);         // FFMA-imm: 0.25(w+tw)
    float m    = fmaxf(fabsf(dc), fabsf(hd));  // FMNMX |src|
    float den  = fmaf(m, 0.5f, hs_h);          // FFMA-imm: 0.5(hs+m)
    float r    = rcp_fast(den);                // MUFU.RCP
    float t    = fabsf(dc) + C;                // FADD |src|
    float l1   = fmaf(fabsf(hd), 2.0f, t);     // FFMA-imm
    return fmaf(m, r, l1);                     // FFMA
}

__global__ __launch_bounds__(NTHREADS)
void hm_cost_kernel(const float* __restrict__ logits,
                    const float* __restrict__ spans,
                    const float* __restrict__ tgt,
                    const float* __restrict__ ref,
                    float* __restrict__ out)
{
    __shared__ float  s_tc[TT], s_htw[TT];   // target cx, 0.5*tw (SoA)
    __shared__ float4 s_row[QPER];           // {cx, 0.5w, 0.25w, cc+cr-1}

    const int tid  = threadIdx.x;
    const int row0 = blockIdx.x * QPER;

    const float2* tg2 = reinterpret_cast<const float2*>(tgt);
    #pragma unroll
    for (int k = 0; k < TT / NTHREADS; k++) {
        int j = tid + k * NTHREADS;
        float2 s = tg2[j];
        s_tc[j]  = s.x;
        s_htw[j] = 0.5f * s.y;
    }

    if (tid < QPER) {
        int r = row0 + tid;
        float2 s  = reinterpret_cast<const float2*>(spans)[r];
        float cx = s.x, hw = 0.5f * s.y;
        float2 lg = reinterpret_cast<const float2*>(logits)[r];
        float cc = -rcp_fast(1.0f + __expf(lg.y - lg.x));   // -softmax prob class 0
        float2 rp = reinterpret_cast<const float2*>(ref)[r];
        float d0 = (cx - hw) - rp.x;
        float d1 = (cx + hw) - rp.y;
        float cr = sqrtf(d0 * d0 + d1 * d1);
        s_row[tid] = make_float4(cx, hw, 0.5f * hw, cc + cr - 1.0f);
    }
    __syncthreads();

    // 8 targets per thread (16 scalar regs), live across all 16 rows.
    const int tb = tid * TPT;
    const float4 tcA = *reinterpret_cast<const float4*>(&s_tc[tb]);
    const float4 tcB = *reinterpret_cast<const float4*>(&s_tc[tb + 4]);
    const float4 htA = *reinterpret_cast<const float4*>(&s_htw[tb]);
    const float4 htB = *reinterpret_cast<const float4*>(&s_htw[tb + 4]);

    float* base = out + (size_t)row0 * TT + tb;

    float4 R = s_row[0];                     // prefetched row constants
    #pragma unroll
    for (int q = 0; q < QPER; q++) {
        const float cx = R.x, hw = R.y, hqq = R.z, C = R.w;
        if (q + 1 < QPER) R = s_row[q + 1];  // prefetch next row (hides LDS lat)

        float4 oA, oB;
        oA.x = cost_el(cx, hw, hqq, C, tcA.x, htA.x);
        oA.y = cost_el(cx, hw, hqq, C, tcA.y, htA.y);
        oA.z = cost_el(cx, hw, hqq, C, tcA.z, htA.z);
        oA.w = cost_el(cx, hw, hqq, C, tcA.w, htA.w);
        oB.x = cost_el(cx, hw, hqq, C, tcB.x, htB.x);
        oB.y = cost_el(cx, hw, hqq, C, tcB.y, htB.y);
        oB.z = cost_el(cx, hw, hqq, C, tcB.z, htB.z);
        oB.w = cost_el(cx, hw, hqq, C, tcB.w, htB.w);
        *reinterpret_cast<float4*>(base + q * TT)     = oA;  // STG.E.128 [R+imm]
        *reinterpret_cast<float4*>(base + q * TT + 4) = oB;
    }
}

extern "C" void kernel_launch(void* const* d_in, const int* in_sizes, int n_in,
                              void* d_out, int out_size)
{
    const float* logits = (const float*)d_in[0];
    const float* spans  = (const float*)d_in[1];
    const float* tgt    = (const float*)d_in[2];
    const float* ref    = (const float*)d_in[3];
    float* out = (float*)d_out;

    hm_cost_kernel<<<NROWS / QPER, NTHREADS>>>(logits, spans, tgt, ref, out);
}